// round 1
// baseline (speedup 1.0000x reference)
#include <cuda_runtime.h>

#define NN 4096
#define CC 128
#define NELLD 9
#define NSPEC 10
#define NPB 4
#define NPERM (NN + NSPEC * NPB)
#define USTRIDE 3276  /* floats per (c,s): 729*4 (u3) + 81*4 (u2) + 9*4 (u1) */

// ---------------- device scratch (no runtime allocation allowed) ----------------
__device__ float g_u[CC * NSPEC * USTRIDE];   // ~16.8 MB: weighted basis per (c, spec)
__device__ float g_f[4 * CC * NN];            // ~8.4 MB: contraction output [o][c][n]
__device__ int   g_perm[NPERM];
__device__ int   g_bstart[NSPEC];
__device__ int   g_bcnt[NSPEC];

// ---------------- kernel 1: bucket nodes by species (NPB-padded buckets) --------
__global__ void bucket_kernel(const int* __restrict__ spec) {
    __shared__ int cnt[NSPEC];
    __shared__ int cur[NSPEC];
    const int tid = threadIdx.x;
    if (tid < NSPEC) cnt[tid] = 0;
    __syncthreads();
    for (int i = tid; i < NN; i += blockDim.x) atomicAdd(&cnt[spec[i]], 1);
    __syncthreads();
    if (tid == 0) {
        int off = 0;
        for (int s = 0; s < NSPEC; ++s) {
            g_bstart[s] = off;
            g_bcnt[s]   = cnt[s];
            cur[s]      = off;
            off += ((cnt[s] + NPB - 1) / NPB) * NPB;
        }
    }
    __syncthreads();
    for (int i = tid; i < NPERM; i += blockDim.x) g_perm[i] = -1;
    __syncthreads();
    for (int i = tid; i < NN; i += blockDim.x) {
        const int s = spec[i];
        const int pos = atomicAdd(&cur[s], 1);
        g_perm[pos] = i;
    }
}

// ---------------- kernel 2: precontract U with per-(spec,channel) weights -------
// layout per (c,s) blob: [729][o4] u3 | [81][o4] u2 | [9][o4] u1, o = {0e, 1o_0, 1o_1, 1o_2}
__global__ void __launch_bounds__(128) precompute_kernel(
    const float* __restrict__ U3_0e, const float* __restrict__ U2_0e, const float* __restrict__ U1_0e,
    const float* __restrict__ W3_0e, const float* __restrict__ W2_0e, const float* __restrict__ W1_0e,
    const float* __restrict__ U3_1o, const float* __restrict__ U2_1o, const float* __restrict__ U1_1o,
    const float* __restrict__ W3_1o, const float* __restrict__ W2_1o, const float* __restrict__ W1_1o) {
    const int c = blockIdx.x, s = blockIdx.y;
    float w3a[4], w3b[4], w2a[2], w2b[2];
#pragma unroll
    for (int k = 0; k < 4; ++k) {
        w3a[k] = W3_0e[(s * 4 + k) * CC + c];
        w3b[k] = W3_1o[(s * 4 + k) * CC + c];
    }
#pragma unroll
    for (int k = 0; k < 2; ++k) {
        w2a[k] = W2_0e[(s * 2 + k) * CC + c];
        w2b[k] = W2_1o[(s * 2 + k) * CC + c];
    }
    const float w1a = W1_0e[s * CC + c];
    const float w1b = W1_1o[s * CC + c];

    float4* dst = reinterpret_cast<float4*>(g_u + (c * NSPEC + s) * USTRIDE);
    for (int idx = threadIdx.x; idx < 729; idx += blockDim.x) {
        float4 v;
        v.x = U3_0e[idx * 4 + 0] * w3a[0] + U3_0e[idx * 4 + 1] * w3a[1] +
              U3_0e[idx * 4 + 2] * w3a[2] + U3_0e[idx * 4 + 3] * w3a[3];
        v.y = U3_1o[idx * 4 + 0] * w3b[0] + U3_1o[idx * 4 + 1] * w3b[1] +
              U3_1o[idx * 4 + 2] * w3b[2] + U3_1o[idx * 4 + 3] * w3b[3];
        v.z = U3_1o[(729 + idx) * 4 + 0] * w3b[0] + U3_1o[(729 + idx) * 4 + 1] * w3b[1] +
              U3_1o[(729 + idx) * 4 + 2] * w3b[2] + U3_1o[(729 + idx) * 4 + 3] * w3b[3];
        v.w = U3_1o[(1458 + idx) * 4 + 0] * w3b[0] + U3_1o[(1458 + idx) * 4 + 1] * w3b[1] +
              U3_1o[(1458 + idx) * 4 + 2] * w3b[2] + U3_1o[(1458 + idx) * 4 + 3] * w3b[3];
        dst[idx] = v;
    }
    float4* dst2 = dst + 729;
    for (int idx = threadIdx.x; idx < 81; idx += blockDim.x) {
        float4 v;
        v.x = U2_0e[idx * 2 + 0] * w2a[0] + U2_0e[idx * 2 + 1] * w2a[1];
        v.y = U2_1o[idx * 2 + 0] * w2b[0] + U2_1o[idx * 2 + 1] * w2b[1];
        v.z = U2_1o[(81 + idx) * 2 + 0] * w2b[0] + U2_1o[(81 + idx) * 2 + 1] * w2b[1];
        v.w = U2_1o[(162 + idx) * 2 + 0] * w2b[0] + U2_1o[(162 + idx) * 2 + 1] * w2b[1];
        dst2[idx] = v;
    }
    float4* dst1 = dst + 810;
    for (int idx = threadIdx.x; idx < 9; idx += blockDim.x) {
        float4 v;
        v.x = U1_0e[idx] * w1a;
        v.y = U1_1o[idx] * w1b;
        v.z = U1_1o[9 + idx] * w1b;
        v.w = U1_1o[18 + idx] * w1b;
        dst1[idx] = v;
    }
}

// ---------------- kernel 3: fused cubic-form contraction ------------------------
// block = (spec s, channel c); smem holds ū(s,c); each thread handles NPB nodes of
// the same species so one broadcast LDS.128 feeds 16 FMAs.
__global__ void __launch_bounds__(128) contract_kernel(const float* __restrict__ x) {
    const int s = blockIdx.x;
    const int c = blockIdx.y;
    __shared__ __align__(16) float su[USTRIDE];
    __shared__ float xsh[128 * 37];  // padded stride 37 -> conflict-free dynamic access

    const float* src = g_u + (c * NSPEC + s) * USTRIDE;
    for (int i = threadIdx.x; i < USTRIDE / 4; i += 128)
        reinterpret_cast<float4*>(su)[i] = reinterpret_cast<const float4*>(src)[i];
    __syncthreads();

    const int cnt = g_bcnt[s];
    const int start = g_bstart[s];
    const int ngroups = (cnt + NPB - 1) / NPB;

    const float4* u3 = reinterpret_cast<const float4*>(su);
    const float4* u2 = reinterpret_cast<const float4*>(su) + 729;
    const float4* u1 = reinterpret_cast<const float4*>(su) + 810;
    float* myx = &xsh[threadIdx.x * 37];

    for (int g = threadIdx.x; g < ngroups; g += 128) {
        int nodes[NPB];
        float xr[NPB][9];  // register copy: only compile-time indexed
#pragma unroll
        for (int j = 0; j < NPB; ++j) {
            const int n = g_perm[start + g * NPB + j];
            nodes[j] = n;
            const float* xp = x + (long)(n < 0 ? 0 : n) * (CC * NELLD) + c * NELLD;
#pragma unroll
            for (int i = 0; i < 9; ++i) xr[j][i] = (n >= 0) ? xp[i] : 0.f;
#pragma unroll
            for (int i = 0; i < 9; ++i) myx[j * 9 + i] = xr[j][i];
        }

        float acc[NPB][4] = {};
#pragma unroll 1
        for (int p = 0; p < 9; ++p) {
            float xp[NPB];
#pragma unroll
            for (int j = 0; j < NPB; ++j) xp[j] = myx[j * 9 + p];  // smem, dynamic p
            const float4 v1 = u1[p];
#pragma unroll
            for (int j = 0; j < NPB; ++j) {
                acc[j][0] += v1.x * xp[j];
                acc[j][1] += v1.y * xp[j];
                acc[j][2] += v1.z * xp[j];
                acc[j][3] += v1.w * xp[j];
            }
            const float4* u2p = u2 + p * 9;
            const float4* u3p = u3 + p * 81;
#pragma unroll
            for (int q = 0; q < 9; ++q) {
                float xpq[NPB];
                const float4 v2 = u2p[q];
#pragma unroll
                for (int j = 0; j < NPB; ++j) {
                    xpq[j] = xp[j] * xr[j][q];
                    acc[j][0] += v2.x * xpq[j];
                    acc[j][1] += v2.y * xpq[j];
                    acc[j][2] += v2.z * xpq[j];
                    acc[j][3] += v2.w * xpq[j];
                }
#pragma unroll
                for (int i = 0; i < 9; ++i) {
                    const float4 v3 = u3p[q * 9 + i];
#pragma unroll
                    for (int j = 0; j < NPB; ++j) {
                        const float m = xpq[j] * xr[j][i];
                        acc[j][0] += v3.x * m;
                        acc[j][1] += v3.y * m;
                        acc[j][2] += v3.z * m;
                        acc[j][3] += v3.w * m;
                    }
                }
            }
        }
#pragma unroll
        for (int j = 0; j < NPB; ++j) {
            if (nodes[j] >= 0) {
#pragma unroll
                for (int o = 0; o < 4; ++o)
                    g_f[(o * CC + c) * NN + nodes[j]] = acc[j][o];
            }
        }
    }
}

// ---------------- kernel 4: e3nn Linear (4 small GEMMs) -------------------------
// y[n,m] = (sum_c f[z][c][n] * W[c][m]) * (1/sqrt(C))  (+ bias for z==0)
__global__ void __launch_bounds__(256) linear_kernel(
    const float* __restrict__ W0, const float* __restrict__ W1,
    const float* __restrict__ bias, float* __restrict__ out) {
    const int z = blockIdx.y;
    const int n0 = blockIdx.x * 128;
    const float* A = g_f + z * (CC * NN);      // [c][n]
    const float* B = (z == 0) ? W0 : W1;       // [c][m]
    __shared__ float As[8][128];
    __shared__ float Bs[8][128];
    const int tid = threadIdx.x;
    const int r = tid >> 4, cix = tid & 15;
    const int lk = tid >> 5, lv = (tid & 31) << 2;
    float acc[8][8] = {};
    for (int kc = 0; kc < CC; kc += 8) {
        *reinterpret_cast<float4*>(&As[lk][lv]) =
            *reinterpret_cast<const float4*>(A + (kc + lk) * NN + n0 + lv);
        *reinterpret_cast<float4*>(&Bs[lk][lv]) =
            *reinterpret_cast<const float4*>(B + (kc + lk) * CC + lv);
        __syncthreads();
#pragma unroll
        for (int k = 0; k < 8; ++k) {
            float a[8], b[8];
#pragma unroll
            for (int i = 0; i < 4; ++i) {
                a[i] = As[k][r * 8 + i];
                a[4 + i] = As[k][r * 8 + 4 + i];
                b[i] = Bs[k][cix * 8 + i];
                b[4 + i] = Bs[k][cix * 8 + 4 + i];
            }
#pragma unroll
            for (int i = 0; i < 8; ++i)
#pragma unroll
                for (int j = 0; j < 8; ++j) acc[i][j] += a[i] * b[j];
        }
        __syncthreads();
    }
    const float scale = 0.088388347648318447f;  // 1/sqrt(128)
#pragma unroll
    for (int i = 0; i < 8; ++i) {
        const int n = n0 + r * 8 + i;
#pragma unroll
        for (int j = 0; j < 8; ++j) {
            const int m = cix * 8 + j;
            const float v = acc[i][j] * scale;
            if (z == 0)
                out[n * 512 + m] = v + bias[m];
            else
                out[n * 512 + 128 + m * 3 + (z - 1)] = v;
        }
    }
}

// ---------------- launch ---------------------------------------------------------
extern "C" void kernel_launch(void* const* d_in, const int* in_sizes, int n_in,
                              void* d_out, int out_size) {
    const float* x     = (const float*)d_in[0];
    const int*   spec  = (const int*)d_in[1];
    const float* U3_0e = (const float*)d_in[2];
    const float* U2_0e = (const float*)d_in[3];
    const float* U1_0e = (const float*)d_in[4];
    const float* W3_0e = (const float*)d_in[5];
    const float* W2_0e = (const float*)d_in[6];
    const float* W1_0e = (const float*)d_in[7];
    const float* U3_1o = (const float*)d_in[8];
    const float* U2_1o = (const float*)d_in[9];
    const float* U1_1o = (const float*)d_in[10];
    const float* W3_1o = (const float*)d_in[11];
    const float* W2_1o = (const float*)d_in[12];
    const float* W1_1o = (const float*)d_in[13];
    const float* Wl0   = (const float*)d_in[14];
    const float* Wl1   = (const float*)d_in[15];
    const float* bias  = (const float*)d_in[16];
    float* out = (float*)d_out;

    bucket_kernel<<<1, 256>>>(spec);
    precompute_kernel<<<dim3(CC, NSPEC), 128>>>(U3_0e, U2_0e, U1_0e, W3_0e, W2_0e, W1_0e,
                                                U3_1o, U2_1o, U1_1o, W3_1o, W2_1o, W1_1o);
    contract_kernel<<<dim3(NSPEC, CC), 128>>>(x);
    linear_kernel<<<dim3(NN / 128, 4), 256>>>(Wl0, Wl1, bias, out);
}